// round 8
// baseline (speedup 1.0000x reference)
#include <cuda_runtime.h>
#include <cuda_bf16.h>

#define BATCH 2
#define NPTS  65536
#define KNN   16
#define DCH   32
#define NTILE 128                       // points per block
#define NELEM (NTILE * KNN)             // 2048 elems per tile
#define NGRP  (NELEM / 4)               // 512 float4 groups per tile

// Tiled two-phase kernel. Phase 1: geometry -> smem (SoA). Phase 2: channel-
// major store loop — the whole block streams ONE contiguous 8KB channel
// region at a time (syncthreads-paced), minimizing concurrent DRAM streams.
__global__ __launch_bounds__(256) void lse_kernel(
    const float* __restrict__ coords,    // (B, N, 3)
    const float* __restrict__ features,  // (B, D, N, 1)
    const int*   __restrict__ idx,       // (B, N, K)
    const float* __restrict__ w,         // (D, 10)
    const float* __restrict__ bias,      // (D,)
    const float* __restrict__ gamma,
    const float* __restrict__ beta,
    const float* __restrict__ mean,
    const float* __restrict__ var,
    float* __restrict__ out)             // (B, 2D, N, K)
{
    __shared__ float s_nx[NELEM], s_ny[NELEM], s_nz[NELEM], s_d[NELEM]; // 32KB
    __shared__ float s_cx[NTILE], s_cy[NTILE], s_cz[NTILE];             // 1.5KB
    __shared__ float4 s_wa[DCH];  // we.x, we.y, we.z, wn.x
    __shared__ float4 s_wb[DCH];  // wn.y, wn.z, wd,   bias'

    int t = threadIdx.x;
    if (t < DCH) {
        float sc = gamma[t] * rsqrtf(var[t] + 1e-5f);
        const float* wr = w + t * 10;
        float w0 = wr[0], w1 = wr[1], w2 = wr[2], w3 = wr[3], w4 = wr[4];
        float w5 = wr[5], w6 = wr[6], w7 = wr[7], w8 = wr[8], w9 = wr[9];
        s_wa[t] = make_float4((w0 + w6) * sc, (w1 + w7) * sc, (w2 + w8) * sc,
                              (w3 - w6) * sc);
        s_wb[t] = make_float4((w4 - w7) * sc, (w5 - w8) * sc, w9 * sc,
                              (bias[t] - mean[t]) * sc + beta[t]);
    }

    int b  = blockIdx.x >> 9;                 // 512 blocks per batch
    int n0 = (blockIdx.x & 511) * NTILE;      // first point of tile

    const float* cb = coords + (size_t)b * NPTS * 3;

    // ---------------- Phase 1: geometry into smem ----------------
#pragma unroll
    for (int gg = 0; gg < 2; gg++) {
        int g  = t + gg * 256;                // group 0..511
        int nl = g >> 2;                      // local point 0..127
        int kq = g & 3;
        int n  = n0 + nl;

        float cx = cb[(size_t)n * 3 + 0];
        float cy = cb[(size_t)n * 3 + 1];
        float cz = cb[(size_t)n * 3 + 2];
        if (kq == 0) { s_cx[nl] = cx; s_cy[nl] = cy; s_cz[nl] = cz; }

        int4 ii = *reinterpret_cast<const int4*>(
            idx + ((size_t)b * NPTS + (size_t)n) * KNN + kq * 4);

        float4 vx, vy, vz, vd;
        float* px = &vx.x; float* py = &vy.x;
        float* pz = &vz.x; float* pd = &vd.x;
#pragma unroll
        for (int j = 0; j < 4; j++) {
            int id = (&ii.x)[j];
            float x = __ldg(cb + (size_t)id * 3 + 0);
            float y = __ldg(cb + (size_t)id * 3 + 1);
            float z = __ldg(cb + (size_t)id * 3 + 2);
            px[j] = x; py[j] = y; pz[j] = z;
            float ddx = cx - x, ddy = cy - y, ddz = cz - z;
            pd[j] = sqrtf(ddx * ddx + ddy * ddy + ddz * ddz);
        }
        *reinterpret_cast<float4*>(s_nx + g * 4) = vx;
        *reinterpret_cast<float4*>(s_ny + g * 4) = vy;
        *reinterpret_cast<float4*>(s_nz + g * 4) = vz;
        *reinterpret_cast<float4*>(s_d  + g * 4) = vd;
    }
    __syncthreads();

    // ---------------- Phase 2a: computed channels ----------------
    const size_t cstride = (size_t)NPTS * KNN;
    // base of this tile in out: channel 0, computed half
    float* outc = out + (size_t)b * 2 * DCH * cstride + (size_t)n0 * KNN;

    int g0  = t;            // group for first quad
    int g1  = t + 256;      // group for second quad
    int nl0 = g0 >> 2, kq0 = g0 & 3;
    int nl1 = g1 >> 2, kq1 = g1 & 3;
    float cx0 = s_cx[nl0], cy0 = s_cy[nl0], cz0 = s_cz[nl0];
    float cx1 = s_cx[nl1], cy1 = s_cy[nl1], cz1 = s_cz[nl1];

    for (int o = 0; o < DCH; o++) {
        float4 wa = s_wa[o];
        float4 wb = s_wb[o];
        float* oc = outc + (size_t)o * cstride;
#pragma unroll
        for (int gg = 0; gg < 2; gg++) {
            int g = gg ? g1 : g0;
            float base = gg
                ? (wb.w + wa.x * cx1 + wa.y * cy1 + wa.z * cz1)
                : (wb.w + wa.x * cx0 + wa.y * cy0 + wa.z * cz0);
            float4 vx = *reinterpret_cast<const float4*>(s_nx + g * 4);
            float4 vy = *reinterpret_cast<const float4*>(s_ny + g * 4);
            float4 vz = *reinterpret_cast<const float4*>(s_nz + g * 4);
            float4 vd = *reinterpret_cast<const float4*>(s_d  + g * 4);
            float4 r;
            r.x = fmaxf(base + wa.w*vx.x + wb.x*vy.x + wb.y*vz.x + wb.z*vd.x, 0.f);
            r.y = fmaxf(base + wa.w*vx.y + wb.x*vy.y + wb.y*vz.y + wb.z*vd.y, 0.f);
            r.z = fmaxf(base + wa.w*vx.z + wb.x*vy.z + wb.y*vz.z + wb.z*vd.z, 0.f);
            r.w = fmaxf(base + wa.w*vx.w + wb.x*vy.w + wb.y*vz.w + wb.z*vd.w, 0.f);
            __stcs(reinterpret_cast<float4*>(oc) + g, r);
        }
        __syncthreads();   // keep the block on one channel region at a time
    }

    // ---------------- Phase 2b: feature-broadcast channels ----------------
    const float* fb = features + (size_t)b * DCH * NPTS + n0;
    float* outf = outc + (size_t)DCH * cstride;
    for (int c = 0; c < DCH; c++) {
        const float* fr = fb + (size_t)c * NPTS;
        float* oc = outf + (size_t)c * cstride;
        float f0 = __ldg(fr + nl0);
        float f1 = __ldg(fr + nl1);
        __stcs(reinterpret_cast<float4*>(oc) + g0, make_float4(f0, f0, f0, f0));
        __stcs(reinterpret_cast<float4*>(oc) + g1, make_float4(f1, f1, f1, f1));
        __syncthreads();
    }
}

extern "C" void kernel_launch(void* const* d_in, const int* in_sizes, int n_in,
                              void* d_out, int out_size) {
    const float* coords   = (const float*)d_in[0];
    const float* features = (const float*)d_in[1];
    const int*   idx      = (const int*)d_in[2];
    const float* w        = (const float*)d_in[3];
    const float* bias     = (const float*)d_in[4];
    const float* gamma    = (const float*)d_in[5];
    const float* beta     = (const float*)d_in[6];
    const float* mean     = (const float*)d_in[7];
    const float* var      = (const float*)d_in[8];
    float* out = (float*)d_out;

    const int blocks = BATCH * NPTS / NTILE;   // 1024
    lse_kernel<<<blocks, 256>>>(coords, features, idx, w, bias,
                                gamma, beta, mean, var, out);
}